// round 7
// baseline (speedup 1.0000x reference)
#include <cuda_runtime.h>
#include <cstdint>

#define NN 8192      // nodes
#define HD 128       // hidden dim
#define EE 16384     // edges
#define EDF 16       // edge feature dim
#define MH 64        // mlp hidden
#define KC2 8320     // (MH+1)*HD columns of U (65th k-block carries b2)
#define G3 384       // 3*HD gate columns

// ---- scratch (static __device__, allocation-guard safe) ----
__device__ float g_hid[EE * MH];            // relu(ef@W1+b1)            (4MB)
__device__ float g_m[NN * HD];              // scatter accumulator       (4MB)
__device__ float g_gi[NN * G3];             // m @ W_ih^T                (12.6MB)
__device__ float g_gh[NN * G3];             // h @ W_hh^T                (12.6MB)
__device__ float g_U[(size_t)NN * KC2];     // per-node transformed      (~273MB)

// ===========================================================================
// helpers
// ===========================================================================
__device__ __forceinline__ float to_tf32(float x) {
    float y;
    asm("cvt.rna.tf32.f32 %0, %1;" : "=f"(y) : "f"(x));
    return y;
}
__device__ __forceinline__ void mma_tf32(float& c0, float& c1, float& c2, float& c3,
                                         uint32_t a0, uint32_t a1, uint32_t a2, uint32_t a3,
                                         uint32_t b0, uint32_t b1) {
    asm volatile(
        "mma.sync.aligned.m16n8k8.row.col.f32.tf32.tf32.f32 "
        "{%0,%1,%2,%3}, {%4,%5,%6,%7}, {%8,%9}, {%0,%1,%2,%3};"
        : "+f"(c0), "+f"(c1), "+f"(c2), "+f"(c3)
        : "r"(a0), "r"(a1), "r"(a2), "r"(a3), "r"(b0), "r"(b1));
}

// ===========================================================================
// hid_kernel: g_hid[e,k] = relu(b1[k] + sum_t ef[e,t]*W1[t,k]); also zeroes g_m
// ===========================================================================
__global__ void hid_kernel(const float* __restrict__ ef, const float* __restrict__ W1,
                           const float* __restrict__ b1) {
    __shared__ float W1s[EDF * MH];
    __shared__ float b1s[MH];
    int tid = threadIdx.x;
    for (int i2 = tid; i2 < EDF * MH; i2 += blockDim.x) W1s[i2] = W1[i2];
    if (tid < MH) b1s[tid] = b1[tid];
    __syncthreads();
    int idx = blockIdx.x * blockDim.x + tid;    // e*64 + k
    int e = idx >> 6, k = idx & 63;
    float acc = b1s[k];
    const float* efe = ef + e * EDF;
    #pragma unroll
    for (int t = 0; t < EDF; t++) acc += efe[t] * W1s[t * MH + k];
    g_hid[idx] = fmaxf(acc, 0.0f);
    g_m[idx] = 0.0f;
}

// ===========================================================================
// u_mma_kernel v2: U[n][col] = sum_j h[n][j] * B[col][j], tf32 mma.sync.
// Fragment-ready swizzled smem layout:
//   A_f[mb(8)][kc(16)][lane(32)][q(4)]  : q = {(g,tg),(g+8,tg),(g,tg+4),(g+8,tg+4)}
//   B_f[nb(16)][kc(16)][lane(32)][qb(2)]: qb = {(g,tg),(g,tg+4)}
//   lane slot XOR-swizzled by (kc&7) -> one-time scatter stores <=2-way,
//   mainloop reads conflict-free LDS.128/LDS.64.
// 2-stage K pipeline: LDG half1 issued before compute half0.
// ===========================================================================
#define U_SMEM_BYTES (2 * 16384 * 4)   // 128 KB

__device__ __forceinline__ void scatter_frag(float* __restrict__ A_f,
                                             float* __restrict__ B_f,
                                             int row, int c4, float4 va, float4 vb) {
    int kc = c4 >> 1;
    int qp = c4 & 1;
    int r = row & 15;
    int qa = qp * 2 + (r >> 3);
    int mb = row >> 4, nb = row >> 3;
    int swz = kc & 7;
    int abase = ((mb * 16 + kc) * 32) * 4;
    int bbase = ((nb * 16 + kc) * 32) * 2;
    float av[4] = {va.x, va.y, va.z, va.w};
    float bv[4] = {vb.x, vb.y, vb.z, vb.w};
    #pragma unroll
    for (int dk = 0; dk < 4; dk++) {
        int L = ((row & 7) * 4 + dk) ^ swz;
        A_f[abase + L * 4 + qa] = to_tf32(av[dk]);
        B_f[bbase + L * 2 + qp] = to_tf32(bv[dk]);
    }
}

__device__ __forceinline__ void compute_half(const float* __restrict__ A_f,
                                             const float* __restrict__ B_f,
                                             int lane, int warp_mb, int warp_nb,
                                             int klo, float acc[2][4][4]) {
    #pragma unroll
    for (int kk = 0; kk < 8; kk++) {
        int kc = klo + kk;
        int Lp = lane ^ (kc & 7);
        float4 af[2];
        float2 bf[4];
        #pragma unroll
        for (int mf = 0; mf < 2; mf++)
            af[mf] = *reinterpret_cast<const float4*>(
                &A_f[(((warp_mb + mf) * 16 + kc) * 32 + Lp) * 4]);
        #pragma unroll
        for (int nf = 0; nf < 4; nf++)
            bf[nf] = *reinterpret_cast<const float2*>(
                &B_f[(((warp_nb + nf) * 16 + kc) * 32 + Lp) * 2]);
        #pragma unroll
        for (int mf = 0; mf < 2; mf++)
            #pragma unroll
            for (int nf = 0; nf < 4; nf++)
                mma_tf32(acc[mf][nf][0], acc[mf][nf][1], acc[mf][nf][2], acc[mf][nf][3],
                         __float_as_uint(af[mf].x), __float_as_uint(af[mf].y),
                         __float_as_uint(af[mf].z), __float_as_uint(af[mf].w),
                         __float_as_uint(bf[nf].x), __float_as_uint(bf[nf].y));
    }
}

__global__ __launch_bounds__(512) void u_mma_kernel(
        const float* __restrict__ hin, const float* __restrict__ W2,
        const float* __restrict__ b2) {
    extern __shared__ float smem[];
    float* A_f = smem;              // 64 KB
    float* B_f = smem + 16384;      // 64 KB

    int tid = threadIdx.x;
    int n0blk = blockIdx.x * 128;
    int colbase = blockIdx.y * 128;

    const float4* A4 = reinterpret_cast<const float4*>(hin + (size_t)n0blk * HD);
    const float*  Bsrc = (blockIdx.y < 64) ? (W2 + (size_t)blockIdx.y * 16384) : b2;
    const float4* B4 = reinterpret_cast<const float4*>(Bsrc);

    float4 va[4], vb[4];
    // ---- load + scatter half 0 (kc 0..7) ----
    #pragma unroll
    for (int p = 0; p < 4; p++) {
        int t = tid + p * 512;
        va[p] = A4[(t >> 4) * 32 + (t & 15)];
        vb[p] = B4[(t >> 4) * 32 + (t & 15)];
    }
    #pragma unroll
    for (int p = 0; p < 4; p++) {
        int t = tid + p * 512;
        scatter_frag(A_f, B_f, t >> 4, t & 15, va[p], vb[p]);
    }
    __syncthreads();

    // ---- issue global loads for half 1 (latency hidden under compute) ----
    #pragma unroll
    for (int p = 0; p < 4; p++) {
        int t = tid + p * 512;
        va[p] = A4[(t >> 4) * 32 + (t & 15) + 16];
        vb[p] = B4[(t >> 4) * 32 + (t & 15) + 16];
    }

    int lane = tid & 31, wid = tid >> 5;
    int warp_mb = (wid & 3) * 2;
    int warp_nb = (wid >> 2) * 4;

    float acc[2][4][4];
    #pragma unroll
    for (int mf = 0; mf < 2; mf++)
        #pragma unroll
        for (int nf = 0; nf < 4; nf++)
            #pragma unroll
            for (int q = 0; q < 4; q++) acc[mf][nf][q] = 0.0f;

    compute_half(A_f, B_f, lane, warp_mb, warp_nb, 0, acc);

    // scatter half 1 (kc 8..15 — disjoint from half 0 reads, no sync needed before)
    #pragma unroll
    for (int p = 0; p < 4; p++) {
        int t = tid + p * 512;
        scatter_frag(A_f, B_f, t >> 4, (t & 15) + 16, va[p], vb[p]);
    }
    __syncthreads();

    compute_half(A_f, B_f, lane, warp_mb, warp_nb, 8, acc);

    // ---- epilogue ----
    int g = lane >> 2, tg = lane & 3;
    int warp_m = (wid & 3) * 32;
    int warp_n = (wid >> 2) * 32;
    #pragma unroll
    for (int mf = 0; mf < 2; mf++) {
        int row = n0blk + warp_m + mf * 16 + g;
        #pragma unroll
        for (int nf = 0; nf < 4; nf++) {
            int col = colbase + warp_n + nf * 8 + 2 * tg;
            float* d0 = g_U + (size_t)row * KC2 + col;
            *reinterpret_cast<float2*>(d0) =
                make_float2(acc[mf][nf][0], acc[mf][nf][1]);
            *reinterpret_cast<float2*>(d0 + (size_t)8 * KC2) =
                make_float2(acc[mf][nf][2], acc[mf][nf][3]);
        }
    }
}

// ===========================================================================
// msg_kernel: one edge per block (unchanged)
// ===========================================================================
__global__ __launch_bounds__(128) void msg_kernel(const int* __restrict__ edge_index) {
    __shared__ float hid_s[MH];
    __shared__ int ssrc, stgt;
    int e = blockIdx.x;
    int tid = threadIdx.x;
    if (tid < MH) hid_s[tid] = g_hid[e * MH + tid];
    if (tid == 0) { ssrc = edge_index[e]; stgt = edge_index[EE + e]; }
    __syncthreads();
    const float* Ur = g_U + (size_t)ssrc * KC2 + tid;
    float a0 = Ur[MH << 7];        // bias row (weight 1)
    float a1 = 0.f, a2 = 0.f, a3 = 0.f;
    #pragma unroll
    for (int k = 0; k < MH; k += 4) {
        float w0 = hid_s[k], w1 = hid_s[k + 1], w2 = hid_s[k + 2], w3 = hid_s[k + 3];
        if (w0 != 0.f) a0 += w0 * Ur[(k    ) << 7];
        if (w1 != 0.f) a1 += w1 * Ur[(k + 1) << 7];
        if (w2 != 0.f) a2 += w2 * Ur[(k + 2) << 7];
        if (w3 != 0.f) a3 += w3 * Ur[(k + 3) << 7];
    }
    atomicAdd(&g_m[stgt * HD + tid], (a0 + a1) + (a2 + a3));
}

// ===========================================================================
// gate_gemm v2: C[n, i] = sum_j A[n,j] * W[i,j]   (fp32, transposed A in smem)
//   z=0: A=g_m, W=W_ih -> g_gi ; z=1: A=h, W=W_hh -> g_gh
// ===========================================================================
#define AT_PAD 68
__global__ __launch_bounds__(128) void gate_gemm(
        const float* __restrict__ hin,
        const float* __restrict__ W_ih, const float* __restrict__ W_hh) {
    __shared__ float A_sT[128][AT_PAD];     // [k][node]
    __shared__ float Ws[16 * 128];          // [kk][col]
    int tid = threadIdx.x;
    int n0 = blockIdx.x * 64;
    int colbase = blockIdx.y * 128;         // 0 / 128 / 256

    const float* A = blockIdx.z ? hin : (const float*)g_m;
    const float* W = blockIdx.z ? W_hh : W_ih;
    float* C = blockIdx.z ? g_gh : g_gi;

    // transposed load: thread tid = j channel, p = local node (coalesced LDG)
    #pragma unroll 8
    for (int p = 0; p < 64; p++)
        A_sT[tid][p] = A[(n0 + p) * HD + tid];
    __syncthreads();

    int ty = tid >> 4, tx = tid & 15;
    float acc[8][8] = {};

    for (int c = 0; c < 8; c++) {           // K=128 in chunks of 16
        int jb = c * 16;
        if (c) __syncthreads();             // WAR on Ws
        // transpose-load W chunk: Ws[kk][col] = W[(colbase+col)*128 + jb+kk]
        #pragma unroll
        for (int p = 0; p < 4; p++) {
            int idx4 = tid + p * 128;       // 0..511
            int col = idx4 >> 2, kq = (idx4 & 3) * 4;
            float4 w = *reinterpret_cast<const float4*>(&W[(colbase + col) * HD + jb + kq]);
            Ws[(kq + 0) * 128 + col] = w.x;
            Ws[(kq + 1) * 128 + col] = w.y;
            Ws[(kq + 2) * 128 + col] = w.z;
            Ws[(kq + 3) * 128 + col] = w.w;
        }
        __syncthreads();
        #pragma unroll 8
        for (int kk = 0; kk < 16; kk++) {
            float4 x0 = *reinterpret_cast<const float4*>(&A_sT[jb + kk][ty * 8]);
            float4 x1 = *reinterpret_cast<const float4*>(&A_sT[jb + kk][ty * 8 + 4]);
            float xv[8] = {x0.x, x0.y, x0.z, x0.w, x1.x, x1.y, x1.z, x1.w};
            float4 w0 = *reinterpret_cast<const float4*>(&Ws[kk * 128 + tx * 8]);
            float4 w1 = *reinterpret_cast<const float4*>(&Ws[kk * 128 + tx * 8 + 4]);
            float wv[8] = {w0.x, w0.y, w0.z, w0.w, w1.x, w1.y, w1.z, w1.w};
            #pragma unroll
            for (int a = 0; a < 8; a++)
                #pragma unroll
                for (int b = 0; b < 8; b++)
                    acc[a][b] += xv[a] * wv[b];
        }
    }
    #pragma unroll
    for (int a = 0; a < 8; a++) {
        int off = (n0 + ty * 8 + a) * G3 + colbase + tx * 8;
        *reinterpret_cast<float4*>(C + off) =
            make_float4(acc[a][0], acc[a][1], acc[a][2], acc[a][3]);
        *reinterpret_cast<float4*>(C + off + 4) =
            make_float4(acc[a][4], acc[a][5], acc[a][6], acc[a][7]);
    }
}

// ===========================================================================
// gru_elem: fused gate nonlinearity + blend (coalesced, memory-bound)
// ===========================================================================
__global__ void gru_elem(const float* __restrict__ hin,
                         const float* __restrict__ b_ih, const float* __restrict__ b_hh,
                         float* __restrict__ out) {
    int idx = blockIdx.x * blockDim.x + threadIdx.x;    // n*128 + i
    int n = idx >> 7, i = idx & 127;
    const float* gi = g_gi + n * G3;
    const float* gh = g_gh + n * G3;
    float r = 1.0f / (1.0f + expf(-(gi[i] + b_ih[i] + gh[i] + b_hh[i])));
    float z = 1.0f / (1.0f + expf(-(gi[HD + i] + b_ih[HD + i] + gh[HD + i] + b_hh[HD + i])));
    float ng = tanhf(gi[2 * HD + i] + b_ih[2 * HD + i]
                     + r * (gh[2 * HD + i] + b_hh[2 * HD + i]));
    float hv = hin[idx];
    out[idx] = (1.0f - z) * ng + z * hv;
}

// ===========================================================================
// metadata order: h, edge_index, edge_features, W1, b1, W2, b2,
//                 W_ih, W_hh, b_ih, b_hh ; output float32 [N, H]
// ===========================================================================
extern "C" void kernel_launch(void* const* d_in, const int* in_sizes, int n_in,
                              void* d_out, int out_size) {
    const float* h_ptr      = (const float*)d_in[0];
    const int*   edge_index = (const int*)  d_in[1];
    const float* ef         = (const float*)d_in[2];
    const float* W1         = (const float*)d_in[3];
    const float* b1         = (const float*)d_in[4];
    const float* W2         = (const float*)d_in[5];
    const float* b2         = (const float*)d_in[6];
    const float* W_ih       = (const float*)d_in[7];
    const float* W_hh       = (const float*)d_in[8];
    const float* b_ih       = (const float*)d_in[9];
    const float* b_hh       = (const float*)d_in[10];
    float* out = (float*)d_out;

    cudaFuncSetAttribute(u_mma_kernel, cudaFuncAttributeMaxDynamicSharedMemorySize,
                         U_SMEM_BYTES);

    hid_kernel<<<(EE * MH) / 256, 256>>>(ef, W1, b1);
    u_mma_kernel<<<dim3(NN / 128, KC2 / 128), 512, U_SMEM_BYTES>>>(h_ptr, W2, b2);
    msg_kernel<<<EE, 128>>>(edge_index);
    gate_gemm<<<dim3(NN / 64, 3, 2), 128>>>(h_ptr, W_ih, W_hh);
    gru_elem<<<(NN * HD) / 256, 256>>>(h_ptr, b_ih, b_hh, out);
}

// round 10
// speedup vs baseline: 1.2045x; 1.2045x over previous
#include <cuda_runtime.h>
#include <cstdint>

#define NN 8192      // nodes
#define HD 128       // hidden dim
#define EE 16384     // edges
#define EDF 16       // edge feature dim
#define MH 64        // mlp hidden
#define KC2 8320     // (MH+1)*HD columns of U (65th k-block carries b2)
#define G3 384       // 3*HD gate columns

// ---- scratch (static __device__, allocation-guard safe) ----
__device__ float g_hid[EE * MH];            // relu(ef@W1+b1)            (4MB)
__device__ float g_m[NN * HD];              // scatter accumulator       (4MB)
__device__ float g_gi[NN * G3];             // m @ W_ih^T                (12.6MB)
__device__ float g_gh[NN * G3];             // h @ W_hh^T                (12.6MB)
__device__ float g_U[(size_t)NN * KC2];     // per-node transformed      (~273MB)

// ===========================================================================
// helpers
// ===========================================================================
__device__ __forceinline__ float to_tf32(float x) {
    float y;
    asm("cvt.rna.tf32.f32 %0, %1;" : "=f"(y) : "f"(x));
    return y;
}
__device__ __forceinline__ void mma_tf32(float& c0, float& c1, float& c2, float& c3,
                                         uint32_t a0, uint32_t a1, uint32_t a2, uint32_t a3,
                                         uint32_t b0, uint32_t b1) {
    asm volatile(
        "mma.sync.aligned.m16n8k8.row.col.f32.tf32.tf32.f32 "
        "{%0,%1,%2,%3}, {%4,%5,%6,%7}, {%8,%9}, {%0,%1,%2,%3};"
        : "+f"(c0), "+f"(c1), "+f"(c2), "+f"(c3)
        : "r"(a0), "r"(a1), "r"(a2), "r"(a3), "r"(b0), "r"(b1));
}

// ===========================================================================
// hid_kernel: g_hid[e,k] = relu(b1[k] + sum_t ef[e,t]*W1[t,k]); also zeroes g_m
// ===========================================================================
__global__ void hid_kernel(const float* __restrict__ ef, const float* __restrict__ W1,
                           const float* __restrict__ b1) {
    __shared__ float W1s[EDF * MH];
    __shared__ float b1s[MH];
    int tid = threadIdx.x;
    for (int i2 = tid; i2 < EDF * MH; i2 += blockDim.x) W1s[i2] = W1[i2];
    if (tid < MH) b1s[tid] = b1[tid];
    __syncthreads();
    int idx = blockIdx.x * blockDim.x + tid;    // e*64 + k
    int e = idx >> 6, k = idx & 63;
    float acc = b1s[k];
    const float* efe = ef + e * EDF;
    #pragma unroll
    for (int t = 0; t < EDF; t++) acc += efe[t] * W1s[t * MH + k];
    g_hid[idx] = fmaxf(acc, 0.0f);
    g_m[idx] = 0.0f;
}

// ===========================================================================
// Shared 128x128x128 tf32 MMA tile (fragment-ready swizzled smem layout):
//   A_f[mb(8)][kc(16)][lane(32)][q(4)]  : q = {(g,tg),(g+8,tg),(g,tg+4),(g+8,tg+4)}
//   B_f[nb(16)][kc(16)][lane(32)][qb(2)]: qb = {(g,tg),(g,tg+4)}
//   lane slot XOR-swizzled by (kc&7); mainloop reads conflict-free LDS.128/64.
// 2-stage K pipeline: LDG half1 issued before compute half0.
// 512 threads, 128 KB dynamic smem.
// ===========================================================================
#define U_SMEM_BYTES (2 * 16384 * 4)   // 128 KB

__device__ __forceinline__ void scatter_frag(float* __restrict__ A_f,
                                             float* __restrict__ B_f,
                                             int row, int c4, float4 va, float4 vb) {
    int kc = c4 >> 1;
    int qp = c4 & 1;
    int r = row & 15;
    int qa = qp * 2 + (r >> 3);
    int mb = row >> 4, nb = row >> 3;
    int swz = kc & 7;
    int abase = ((mb * 16 + kc) * 32) * 4;
    int bbase = ((nb * 16 + kc) * 32) * 2;
    float av[4] = {va.x, va.y, va.z, va.w};
    float bv[4] = {vb.x, vb.y, vb.z, vb.w};
    #pragma unroll
    for (int dk = 0; dk < 4; dk++) {
        int L = ((row & 7) * 4 + dk) ^ swz;
        A_f[abase + L * 4 + qa] = to_tf32(av[dk]);
        B_f[bbase + L * 2 + qp] = to_tf32(bv[dk]);
    }
}

__device__ __forceinline__ void compute_half(const float* __restrict__ A_f,
                                             const float* __restrict__ B_f,
                                             int lane, int warp_mb, int warp_nb,
                                             int klo, float acc[2][4][4]) {
    #pragma unroll
    for (int kk = 0; kk < 8; kk++) {
        int kc = klo + kk;
        int Lp = lane ^ (kc & 7);
        float4 af[2];
        float2 bf[4];
        #pragma unroll
        for (int mf = 0; mf < 2; mf++)
            af[mf] = *reinterpret_cast<const float4*>(
                &A_f[(((warp_mb + mf) * 16 + kc) * 32 + Lp) * 4]);
        #pragma unroll
        for (int nf = 0; nf < 4; nf++)
            bf[nf] = *reinterpret_cast<const float2*>(
                &B_f[(((warp_nb + nf) * 16 + kc) * 32 + Lp) * 2]);
        #pragma unroll
        for (int mf = 0; mf < 2; mf++)
            #pragma unroll
            for (int nf = 0; nf < 4; nf++)
                mma_tf32(acc[mf][nf][0], acc[mf][nf][1], acc[mf][nf][2], acc[mf][nf][3],
                         __float_as_uint(af[mf].x), __float_as_uint(af[mf].y),
                         __float_as_uint(af[mf].z), __float_as_uint(af[mf].w),
                         __float_as_uint(bf[nf].x), __float_as_uint(bf[nf].y));
    }
}

// Full tile: C[128,128] (at Cbase, leading dim ldc) = A[128,128] @ B[128,128]^T
__device__ __forceinline__ void gemm128x128(const float4* __restrict__ A4,
                                            const float4* __restrict__ B4,
                                            float* __restrict__ Cbase, size_t ldc,
                                            float* A_f, float* B_f) {
    int tid = threadIdx.x;

    float4 va[4], vb[4];
    #pragma unroll
    for (int p = 0; p < 4; p++) {
        int t = tid + p * 512;
        va[p] = A4[(t >> 4) * 32 + (t & 15)];
        vb[p] = B4[(t >> 4) * 32 + (t & 15)];
    }
    #pragma unroll
    for (int p = 0; p < 4; p++) {
        int t = tid + p * 512;
        scatter_frag(A_f, B_f, t >> 4, t & 15, va[p], vb[p]);
    }
    __syncthreads();

    // issue global loads for half 1 (latency hidden under compute half 0)
    #pragma unroll
    for (int p = 0; p < 4; p++) {
        int t = tid + p * 512;
        va[p] = A4[(t >> 4) * 32 + (t & 15) + 16];
        vb[p] = B4[(t >> 4) * 32 + (t & 15) + 16];
    }

    int lane = tid & 31, wid = tid >> 5;
    int warp_mb = (wid & 3) * 2;
    int warp_nb = (wid >> 2) * 4;

    float acc[2][4][4];
    #pragma unroll
    for (int mf = 0; mf < 2; mf++)
        #pragma unroll
        for (int nf = 0; nf < 4; nf++)
            #pragma unroll
            for (int q = 0; q < 4; q++) acc[mf][nf][q] = 0.0f;

    compute_half(A_f, B_f, lane, warp_mb, warp_nb, 0, acc);

    #pragma unroll
    for (int p = 0; p < 4; p++) {
        int t = tid + p * 512;
        scatter_frag(A_f, B_f, t >> 4, (t & 15) + 16, va[p], vb[p]);
    }
    __syncthreads();

    compute_half(A_f, B_f, lane, warp_mb, warp_nb, 8, acc);

    int g = lane >> 2, tg = lane & 3;
    int warp_m = (wid & 3) * 32;
    int warp_n = (wid >> 2) * 32;
    #pragma unroll
    for (int mf = 0; mf < 2; mf++) {
        int row = warp_m + mf * 16 + g;
        #pragma unroll
        for (int nf = 0; nf < 4; nf++) {
            int col = warp_n + nf * 8 + 2 * tg;
            float* d0 = Cbase + (size_t)row * ldc + col;
            *reinterpret_cast<float2*>(d0) =
                make_float2(acc[mf][nf][0], acc[mf][nf][1]);
            *reinterpret_cast<float2*>(d0 + (size_t)8 * ldc) =
                make_float2(acc[mf][nf][2], acc[mf][nf][3]);
        }
    }
}

// ===========================================================================
// u_mma_kernel: U[n][col] = sum_j h[n][j] * B[col][j]  (col = k*128+i)
// ===========================================================================
__global__ __launch_bounds__(512) void u_mma_kernel(
        const float* __restrict__ hin, const float* __restrict__ W2,
        const float* __restrict__ b2) {
    extern __shared__ float smem[];
    int n0blk = blockIdx.x * 128;
    int colbase = blockIdx.y * 128;
    const float4* A4 = reinterpret_cast<const float4*>(hin + (size_t)n0blk * HD);
    const float*  Bsrc = (blockIdx.y < 64) ? (W2 + (size_t)blockIdx.y * 16384) : b2;
    gemm128x128(A4, reinterpret_cast<const float4*>(Bsrc),
                g_U + (size_t)n0blk * KC2 + colbase, KC2,
                smem, smem + 16384);
}

// ===========================================================================
// gate_mma_kernel: C[n,i] = sum_j A[n,j]*W[i,j]  (tf32 mma)
//   z=0: A=g_m, W=W_ih -> g_gi ; z=1: A=h, W=W_hh -> g_gh
// ===========================================================================
__global__ __launch_bounds__(512) void gate_mma_kernel(
        const float* __restrict__ hin,
        const float* __restrict__ W_ih, const float* __restrict__ W_hh) {
    extern __shared__ float smem[];
    int n0 = blockIdx.x * 128;
    int colbase = blockIdx.y * 128;         // 0 / 128 / 256
    const float* A = blockIdx.z ? hin : (const float*)g_m;
    const float* W = blockIdx.z ? W_hh : W_ih;
    float* C = blockIdx.z ? g_gh : g_gi;
    gemm128x128(reinterpret_cast<const float4*>(A + (size_t)n0 * HD),
                reinterpret_cast<const float4*>(W + (size_t)colbase * HD),
                C + (size_t)n0 * G3 + colbase, G3,
                smem, smem + 16384);
}

// ===========================================================================
// msg_kernel v3: warp per edge. Lane l owns float4 columns [4l,4l+4).
//   messages[e] = U[src][64-block] (bias, w=1) + sum_k hid[e,k]*U[src][k-block]
//   Predicated LDG.128 skips relu-zeroed k (uniform predicate per warp).
// ===========================================================================
#define MEB 8   // edges per block (8 warps, 256 threads)
__global__ __launch_bounds__(256) void msg_kernel(const int* __restrict__ edge_index) {
    __shared__ float hid_s[MEB][MH];
    __shared__ int s_src[MEB], s_tgt[MEB];
    int tid = threadIdx.x;
    int e0 = blockIdx.x * MEB;
    if (tid < MEB) {
        s_src[tid] = edge_index[e0 + tid];
        s_tgt[tid] = edge_index[EE + e0 + tid];
    }
    for (int idx = tid; idx < MEB * MH; idx += 256)
        hid_s[idx >> 6][idx & 63] = g_hid[e0 * MH + idx];
    __syncthreads();

    int we = tid >> 5, lane = tid & 31;
    const float4* Ur = reinterpret_cast<const float4*>(
        g_U + (size_t)s_src[we] * KC2) + lane;

    float4 a0 = Ur[MH * 32];                // bias block, weight 1
    float4 a1 = make_float4(0.f, 0.f, 0.f, 0.f);
    #pragma unroll 8
    for (int k = 0; k < MH; k += 2) {
        float w0 = hid_s[we][k], w1 = hid_s[we][k + 1];
        if (w0 != 0.f) {
            float4 v = Ur[k * 32];
            a0.x += w0 * v.x; a0.y += w0 * v.y; a0.z += w0 * v.z; a0.w += w0 * v.w;
        }
        if (w1 != 0.f) {
            float4 v = Ur[(k + 1) * 32];
            a1.x += w1 * v.x; a1.y += w1 * v.y; a1.z += w1 * v.z; a1.w += w1 * v.w;
        }
    }
    float* mdst = g_m + s_tgt[we] * HD + lane * 4;
    atomicAdd(mdst + 0, a0.x + a1.x);
    atomicAdd(mdst + 1, a0.y + a1.y);
    atomicAdd(mdst + 2, a0.z + a1.z);
    atomicAdd(mdst + 3, a0.w + a1.w);
}

// ===========================================================================
// gru_elem: fused gate nonlinearity + blend (coalesced, memory-bound)
// ===========================================================================
__global__ void gru_elem(const float* __restrict__ hin,
                         const float* __restrict__ b_ih, const float* __restrict__ b_hh,
                         float* __restrict__ out) {
    int idx = blockIdx.x * blockDim.x + threadIdx.x;    // n*128 + i
    int n = idx >> 7, i = idx & 127;
    const float* gi = g_gi + n * G3;
    const float* gh = g_gh + n * G3;
    float r = 1.0f / (1.0f + expf(-(gi[i] + b_ih[i] + gh[i] + b_hh[i])));
    float z = 1.0f / (1.0f + expf(-(gi[HD + i] + b_ih[HD + i] + gh[HD + i] + b_hh[HD + i])));
    float ng = tanhf(gi[2 * HD + i] + b_ih[2 * HD + i]
                     + r * (gh[2 * HD + i] + b_hh[2 * HD + i]));
    float hv = hin[idx];
    out[idx] = (1.0f - z) * ng + z * hv;
}

// ===========================================================================
// metadata order: h, edge_index, edge_features, W1, b1, W2, b2,
//                 W_ih, W_hh, b_ih, b_hh ; output float32 [N, H]
// ===========================================================================
extern "C" void kernel_launch(void* const* d_in, const int* in_sizes, int n_in,
                              void* d_out, int out_size) {
    const float* h_ptr      = (const float*)d_in[0];
    const int*   edge_index = (const int*)  d_in[1];
    const float* ef         = (const float*)d_in[2];
    const float* W1         = (const float*)d_in[3];
    const float* b1         = (const float*)d_in[4];
    const float* W2         = (const float*)d_in[5];
    const float* b2         = (const float*)d_in[6];
    const float* W_ih       = (const float*)d_in[7];
    const float* W_hh       = (const float*)d_in[8];
    const float* b_ih       = (const float*)d_in[9];
    const float* b_hh       = (const float*)d_in[10];
    float* out = (float*)d_out;

    cudaFuncSetAttribute(u_mma_kernel, cudaFuncAttributeMaxDynamicSharedMemorySize,
                         U_SMEM_BYTES);
    cudaFuncSetAttribute(gate_mma_kernel, cudaFuncAttributeMaxDynamicSharedMemorySize,
                         U_SMEM_BYTES);

    hid_kernel<<<(EE * MH) / 256, 256>>>(ef, W1, b1);
    u_mma_kernel<<<dim3(NN / 128, KC2 / 128), 512, U_SMEM_BYTES>>>(h_ptr, W2, b2);
    msg_kernel<<<EE / MEB, 256>>>(edge_index);
    gate_mma_kernel<<<dim3(NN / 128, 3, 2), 512, U_SMEM_BYTES>>>(h_ptr, W_ih, W_hh);
    gru_elem<<<(NN * HD) / 256, 256>>>(h_ptr, b_ih, b_hh, out);
}